// round 3
// baseline (speedup 1.0000x reference)
#include <cuda_runtime.h>
#include <math.h>

#define BATCH 16
#define CDIM  512
#define HH    64
#define WW    64
#define NDIM  4096  // H*W

// 16 MB scratch for energy/attention (in-place softmax), allocation-guard safe.
__device__ float g_energy[BATCH * (size_t)CDIM * CDIM];

// ---------------------------------------------------------------------------
// GEMM1: energy[b,c,d] = sum_n q[b,c,n] * kv[b,d,n]
// A = q (x_pre), B = kv (x_training); both K-major (n contiguous).
// Tile: 128 (c) x 64 (d), K-chunk 32. 256 threads, 8x4 micro-tile.
// ---------------------------------------------------------------------------
__global__ __launch_bounds__(256) void gemm1_kernel(const float* __restrict__ q,
                                                    const float* __restrict__ kv) {
    __shared__ float As[128][33];
    __shared__ float Bs[64][33];

    const int b = blockIdx.z;
    const float* Ab = q  + (size_t)b * CDIM * NDIM + (size_t)blockIdx.y * 128 * NDIM;
    const float* Bb = kv + (size_t)b * CDIM * NDIM + (size_t)blockIdx.x * 64  * NDIM;

    const int t    = threadIdx.x;
    const int lane = t & 31;
    const int w    = t >> 5;       // warp id 0..7
    const int tx   = t & 15;       // 4 d-cols each
    const int ty   = t >> 4;       // 8 c-rows each

    float acc[8][4];
#pragma unroll
    for (int i = 0; i < 8; i++)
#pragma unroll
        for (int j = 0; j < 4; j++) acc[i][j] = 0.0f;

    for (int k0 = 0; k0 < NDIM; k0 += 32) {
        // Load A tile: 128 rows x 32 k (coalesced: one row of 32 per warp)
#pragma unroll
        for (int i = 0; i < 16; i++) {
            int r = i * 8 + w;
            As[r][lane] = Ab[(size_t)r * NDIM + k0 + lane];
        }
        // Load B tile: 64 rows x 32 k
#pragma unroll
        for (int i = 0; i < 8; i++) {
            int r = i * 8 + w;
            Bs[r][lane] = Bb[(size_t)r * NDIM + k0 + lane];
        }
        __syncthreads();

#pragma unroll
        for (int kk = 0; kk < 32; kk++) {
            float a[8], bb[4];
#pragma unroll
            for (int i = 0; i < 8; i++) a[i] = As[ty * 8 + i][kk];
#pragma unroll
            for (int j = 0; j < 4; j++) bb[j] = Bs[tx * 4 + j][kk];
#pragma unroll
            for (int i = 0; i < 8; i++)
#pragma unroll
                for (int j = 0; j < 4; j++) acc[i][j] += a[i] * bb[j];
        }
        __syncthreads();
    }

    float* Eb = g_energy + (size_t)b * CDIM * CDIM;
    const int c0 = blockIdx.y * 128 + ty * 8;
    const int d0 = blockIdx.x * 64 + tx * 4;
#pragma unroll
    for (int i = 0; i < 8; i++)
#pragma unroll
        for (int j = 0; j < 4; j++)
            Eb[(size_t)(c0 + i) * CDIM + d0 + j] = acc[i][j];
}

// ---------------------------------------------------------------------------
// Attention softmax (in place over g_energy):
// att[d] = exp(min_e - e[d]) / sum_d exp(min_e - e[d])
// (softmax(max - e) with its own max-subtract reduces to exactly this)
// One block (128 threads) per (b,c) row of 512.
// ---------------------------------------------------------------------------
__global__ __launch_bounds__(128) void attn_softmax_kernel() {
    float* E = g_energy + (size_t)blockIdx.x * CDIM;
    const int t    = threadIdx.x;
    const int lane = t & 31;
    const int w    = t >> 5;
    __shared__ float red[4];

    float v[4];
#pragma unroll
    for (int i = 0; i < 4; i++) v[i] = E[t + i * 128];

    // min-reduce
    float mn = fminf(fminf(v[0], v[1]), fminf(v[2], v[3]));
#pragma unroll
    for (int off = 16; off > 0; off >>= 1)
        mn = fminf(mn, __shfl_xor_sync(0xffffffffu, mn, off));
    if (lane == 0) red[w] = mn;
    __syncthreads();
    mn = fminf(fminf(red[0], red[1]), fminf(red[2], red[3]));
    __syncthreads();

    // exp + sum-reduce
    float s = 0.0f;
#pragma unroll
    for (int i = 0; i < 4; i++) {
        v[i] = expf(mn - v[i]);
        s += v[i];
    }
#pragma unroll
    for (int off = 16; off > 0; off >>= 1)
        s += __shfl_xor_sync(0xffffffffu, s, off);
    if (lane == 0) red[w] = s;
    __syncthreads();
    s = red[0] + red[1] + red[2] + red[3];

    const float inv = 1.0f / s;
#pragma unroll
    for (int i = 0; i < 4; i++) E[t + i * 128] = v[i] * inv;
}

// ---------------------------------------------------------------------------
// GEMM2: out[b,c,n] = sum_d att[b,c,d] * kv[b,d,n]
// A = attention (K-major, d contiguous), B = kv (N-major, n contiguous).
// Tile: 128 (c) x 64 (n), K-chunk 32.
// ---------------------------------------------------------------------------
__global__ __launch_bounds__(256) void gemm2_kernel(const float* __restrict__ kv,
                                                    float* __restrict__ out) {
    __shared__ float As[128][33];
    __shared__ float Bs[32][64];

    const int b = blockIdx.z;
    const float* Ab = g_energy + (size_t)b * CDIM * CDIM + (size_t)blockIdx.y * 128 * CDIM;
    const float* Bb = kv + (size_t)b * CDIM * NDIM;
    const int n0 = blockIdx.x * 64;

    const int t    = threadIdx.x;
    const int lane = t & 31;
    const int w    = t >> 5;
    const int tx   = t & 15;
    const int ty   = t >> 4;

    float acc[8][4];
#pragma unroll
    for (int i = 0; i < 8; i++)
#pragma unroll
        for (int j = 0; j < 4; j++) acc[i][j] = 0.0f;

    for (int k0 = 0; k0 < CDIM; k0 += 32) {
        // A tile: 128 c-rows x 32 d
#pragma unroll
        for (int i = 0; i < 16; i++) {
            int r = i * 8 + w;
            As[r][lane] = Ab[(size_t)r * CDIM + k0 + lane];
        }
        // B tile: 32 d-rows x 64 n (coalesced halves of rows)
#pragma unroll
        for (int i = 0; i < 8; i++) {
            int e = i * 256 + t;
            int r = e >> 6;
            int n = e & 63;
            Bs[r][n] = Bb[(size_t)(k0 + r) * NDIM + n0 + n];
        }
        __syncthreads();

#pragma unroll
        for (int kk = 0; kk < 32; kk++) {
            float a[8];
#pragma unroll
            for (int i = 0; i < 8; i++) a[i] = As[ty * 8 + i][kk];
            float4 b4 = *(const float4*)&Bs[kk][tx * 4];
#pragma unroll
            for (int i = 0; i < 8; i++) {
                acc[i][0] += a[i] * b4.x;
                acc[i][1] += a[i] * b4.y;
                acc[i][2] += a[i] * b4.z;
                acc[i][3] += a[i] * b4.w;
            }
        }
        __syncthreads();
    }

    float* Ob = out + (size_t)b * CDIM * NDIM;
    const int c0 = blockIdx.y * 128 + ty * 8;
#pragma unroll
    for (int i = 0; i < 8; i++)
#pragma unroll
        for (int j = 0; j < 4; j++)
            Ob[(size_t)(c0 + i) * NDIM + n0 + tx * 4 + j] = acc[i][j];
}

// ---------------------------------------------------------------------------
// Final softmax over W=64, in place on d_out. One warp per row of 64.
// ---------------------------------------------------------------------------
__global__ __launch_bounds__(256) void out_softmax_kernel(float* __restrict__ out) {
    const int t    = threadIdx.x;
    const int lane = t & 31;
    const size_t row = (size_t)blockIdx.x * 8 + (t >> 5);
    float* R = out + row * WW;

    float v0 = R[lane];
    float v1 = R[lane + 32];
    float m = fmaxf(v0, v1);
#pragma unroll
    for (int off = 16; off > 0; off >>= 1)
        m = fmaxf(m, __shfl_xor_sync(0xffffffffu, m, off));
    float e0 = expf(v0 - m);
    float e1 = expf(v1 - m);
    float s = e0 + e1;
#pragma unroll
    for (int off = 16; off > 0; off >>= 1)
        s += __shfl_xor_sync(0xffffffffu, s, off);
    const float inv = 1.0f / s;
    R[lane]      = e0 * inv;
    R[lane + 32] = e1 * inv;
}

// ---------------------------------------------------------------------------
extern "C" void kernel_launch(void* const* d_in, const int* in_sizes, int n_in,
                              void* d_out, int out_size) {
    const float* kv = (const float*)d_in[0];  // x_training
    const float* q  = (const float*)d_in[1];  // x_pre
    float* out = (float*)d_out;

    dim3 g1(CDIM / 64, CDIM / 128, BATCH);   // (8, 4, 16)
    gemm1_kernel<<<g1, 256>>>(q, kv);

    attn_softmax_kernel<<<BATCH * CDIM, 128>>>();

    dim3 g2(NDIM / 64, CDIM / 128, BATCH);   // (64, 4, 16)
    gemm2_kernel<<<g2, 256>>>(kv, out);

    out_softmax_kernel<<<(BATCH * CDIM * HH) / 8, 256>>>(out);
}

// round 5
// speedup vs baseline: 1.6831x; 1.6831x over previous
#include <cuda_runtime.h>
#include <math.h>

#define BATCH 16
#define CDIM  512
#define HH    64
#define WW    64
#define NDIM  4096  // H*W

// 16 MB scratch for energy, allocation-guard safe.
__device__ float g_energy[BATCH * (size_t)CDIM * CDIM];

// ---------------------------------------------------------------------------
// GEMM1: energy[b,c,d] = sum_n q[b,c,n] * kv[b,d,n]
// Tile: 128 (c) x 64 (d), K-chunk 32. 256 threads, 8x4 micro-tile.
// (~fp32 FFMA roofline already; tensor-core port is next round's work)
// ---------------------------------------------------------------------------
__global__ __launch_bounds__(256) void gemm1_kernel(const float* __restrict__ q,
                                                    const float* __restrict__ kv) {
    __shared__ float As[128][33];
    __shared__ float Bs[64][33];

    const int b = blockIdx.z;
    const float* Ab = q  + (size_t)b * CDIM * NDIM + (size_t)blockIdx.y * 128 * NDIM;
    const float* Bb = kv + (size_t)b * CDIM * NDIM + (size_t)blockIdx.x * 64  * NDIM;

    const int t    = threadIdx.x;
    const int lane = t & 31;
    const int w    = t >> 5;
    const int tx   = t & 15;
    const int ty   = t >> 4;

    float acc[8][4];
#pragma unroll
    for (int i = 0; i < 8; i++)
#pragma unroll
        for (int j = 0; j < 4; j++) acc[i][j] = 0.0f;

    for (int k0 = 0; k0 < NDIM; k0 += 32) {
#pragma unroll
        for (int i = 0; i < 16; i++) {
            int r = i * 8 + w;
            As[r][lane] = Ab[(size_t)r * NDIM + k0 + lane];
        }
#pragma unroll
        for (int i = 0; i < 8; i++) {
            int r = i * 8 + w;
            Bs[r][lane] = Bb[(size_t)r * NDIM + k0 + lane];
        }
        __syncthreads();

#pragma unroll
        for (int kk = 0; kk < 32; kk++) {
            float a[8], bb[4];
#pragma unroll
            for (int i = 0; i < 8; i++) a[i] = As[ty * 8 + i][kk];
#pragma unroll
            for (int j = 0; j < 4; j++) bb[j] = Bs[tx * 4 + j][kk];
#pragma unroll
            for (int i = 0; i < 8; i++)
#pragma unroll
                for (int j = 0; j < 4; j++) acc[i][j] += a[i] * bb[j];
        }
        __syncthreads();
    }

    float* Eb = g_energy + (size_t)b * CDIM * CDIM;
    const int c0 = blockIdx.y * 128 + ty * 8;
    const int d0 = blockIdx.x * 64 + tx * 4;
#pragma unroll
    for (int i = 0; i < 8; i++)
#pragma unroll
        for (int j = 0; j < 4; j++)
            Eb[(size_t)(c0 + i) * CDIM + d0 + j] = acc[i][j];
}

// ---------------------------------------------------------------------------
// Fused attention-apply:
//   att[d] = exp(min_e - e[d]) / sum_d exp(min_e - e[d])   (exact denominator)
//   out[c,:] = sum_{d: e[d]-min < 34} att[d] * kv[d,:]     (dropped terms < 2e-15)
//   then softmax over each 64-wide (W) segment, written straight to d_out.
// One block (256 threads) per (b,c) row. kv per batch = 8 MB -> L2-resident.
// ---------------------------------------------------------------------------
__global__ __launch_bounds__(256) void attn_apply_kernel(const float* __restrict__ kv,
                                                         float* __restrict__ out) {
    const int row = blockIdx.x;            // b*512 + c
    const int b   = row >> 9;
    const float* E   = g_energy + (size_t)row * CDIM;
    const float* kvb = kv + (size_t)b * CDIM * NDIM;
    float* O = out + (size_t)row * NDIM;

    __shared__ float sRed[8];
    __shared__ float sW[CDIM];
    __shared__ int   sIdx[CDIM];
    __shared__ int   sCount;
    __shared__ float sOut[NDIM];

    const int t    = threadIdx.x;
    const int lane = t & 31;
    const int wp   = t >> 5;

    const float e0 = E[t];
    const float e1 = E[t + 256];

    // ---- exact min over the 512 energies ----
    float mn = fminf(e0, e1);
#pragma unroll
    for (int off = 16; off > 0; off >>= 1)
        mn = fminf(mn, __shfl_xor_sync(0xffffffffu, mn, off));
    if (lane == 0) sRed[wp] = mn;
    if (t == 0) sCount = 0;
    __syncthreads();
    mn = sRed[0];
#pragma unroll
    for (int i = 1; i < 8; i++) mn = fminf(mn, sRed[i]);
    __syncthreads();   // protect sRed before reuse

    // ---- exact softmax denominator (all 512 terms) ----
    const float p0 = expf(mn - e0);
    const float p1 = expf(mn - e1);
    float s = p0 + p1;
#pragma unroll
    for (int off = 16; off > 0; off >>= 1)
        s += __shfl_xor_sync(0xffffffffu, s, off);
    if (lane == 0) sRed[wp] = s;
    __syncthreads();
    s = 0.0f;
#pragma unroll
    for (int i = 0; i < 8; i++) s += sRed[i];
    const float inv = 1.0f / s;

    // ---- select significant channels (weight >= ~1.7e-15) ----
    if (e0 - mn < 34.0f) {
        int k = atomicAdd(&sCount, 1);
        sIdx[k] = t;       sW[k] = p0 * inv;
    }
    if (e1 - mn < 34.0f) {
        int k = atomicAdd(&sCount, 1);
        sIdx[k] = t + 256; sW[k] = p1 * inv;
    }
    __syncthreads();
    const int cnt = sCount;

    // ---- sparse gather-accumulate: out_row = sum_i w_i * kv[d_i, :] ----
    float acc[16];
#pragma unroll
    for (int k = 0; k < 16; k++) acc[k] = 0.0f;

    for (int i = 0; i < cnt; i++) {
        const float* kr = kvb + (size_t)sIdx[i] * NDIM;
        const float w = sW[i];
#pragma unroll
        for (int k = 0; k < 16; k++)
            acc[k] += w * __ldg(&kr[t + 256 * k]);
    }
#pragma unroll
    for (int k = 0; k < 16; k++) sOut[t + 256 * k] = acc[k];
    __syncthreads();

    // ---- final softmax over each 64-wide segment; 8 warps x 8 segments ----
#pragma unroll
    for (int sgi = 0; sgi < 8; sgi++) {
        const int base = (wp * 8 + sgi) * 64;
        const float v0 = sOut[base + lane];
        const float v1 = sOut[base + lane + 32];
        float m = fmaxf(v0, v1);
#pragma unroll
        for (int off = 16; off > 0; off >>= 1)
            m = fmaxf(m, __shfl_xor_sync(0xffffffffu, m, off));
        const float q0 = expf(v0 - m);
        const float q1 = expf(v1 - m);
        float ss = q0 + q1;
#pragma unroll
        for (int off = 16; off > 0; off >>= 1)
            ss += __shfl_xor_sync(0xffffffffu, ss, off);
        const float iv = 1.0f / ss;
        O[base + lane]      = q0 * iv;
        O[base + lane + 32] = q1 * iv;
    }
}

// ---------------------------------------------------------------------------
extern "C" void kernel_launch(void* const* d_in, const int* in_sizes, int n_in,
                              void* d_out, int out_size) {
    const float* kv = (const float*)d_in[0];  // x_training
    const float* q  = (const float*)d_in[1];  // x_pre
    float* out = (float*)d_out;

    dim3 g1(CDIM / 64, CDIM / 128, BATCH);   // (8, 4, 16)
    gemm1_kernel<<<g1, 256>>>(q, kv);

    attn_apply_kernel<<<BATCH * CDIM, 256>>>(kv, out);
}

// round 10
// speedup vs baseline: 5.1145x; 3.0387x over previous
#include <cuda_runtime.h>
#include <cuda_fp16.h>
#include <cstdint>
#include <math.h>

#define BATCH 16
#define CDIM  512
#define HH    64
#define WW    64
#define NDIM  4096  // H*W
#define TOT_ELEMS (BATCH * CDIM * NDIM)   // 33,554,432

// Scratch (allocation-guard safe): fp16 copies of inputs + fp32 energy.
__device__ __half g_hq [TOT_ELEMS];
__device__ __half g_hkv[TOT_ELEMS];
__device__ float  g_energy[BATCH * (size_t)CDIM * CDIM];

// ---------------------------------------------------------------------------
// Convert fp32 inputs to fp16 scratch. One float4 per tensor per thread.
// ---------------------------------------------------------------------------
__global__ __launch_bounds__(256) void convert_kernel(const float4* __restrict__ q4,
                                                      const float4* __restrict__ kv4) {
    const int i = blockIdx.x * 256 + threadIdx.x;     // < TOT_ELEMS/4
    float4 a = q4[i];
    float4 b = kv4[i];
    __half2* hq  = (__half2*)g_hq;
    __half2* hkv = (__half2*)g_hkv;
    hq [2 * i]     = __floats2half2_rn(a.x, a.y);
    hq [2 * i + 1] = __floats2half2_rn(a.z, a.w);
    hkv[2 * i]     = __floats2half2_rn(b.x, b.y);
    hkv[2 * i + 1] = __floats2half2_rn(b.z, b.w);
}

// ---------------------------------------------------------------------------
// HGEMM: approx energy[b,c,d] = sum_n q[c,n]*kv[d,n], fp16 in, fp32 acc.
// Tile BM=128 x BN=64, BK=64 halves (128 B rows, SW128-style xor swizzle).
// 256 threads = 8 warps (4 along m x 2 along n), warp tile 32x32,
// mma.sync.m16n8k16 fragments via ldmatrix.
// ---------------------------------------------------------------------------
#define BM 128
#define BN 64
#define BK 64

__device__ __forceinline__ int sw_idx(int row, int chunk) {
    // row*BK + swizzled 8-half chunk offset
    return row * BK + ((chunk ^ (row & 7)) << 3);
}

__device__ __forceinline__ void ldsm4(uint32_t& r0, uint32_t& r1, uint32_t& r2,
                                      uint32_t& r3, uint32_t addr) {
    asm volatile("ldmatrix.sync.aligned.m8n8.x4.shared.b16 {%0,%1,%2,%3}, [%4];"
                 : "=r"(r0), "=r"(r1), "=r"(r2), "=r"(r3) : "r"(addr));
}

__device__ __forceinline__ void mma16816(float* c, const uint32_t* a, const uint32_t* b) {
    asm volatile("mma.sync.aligned.m16n8k16.row.col.f32.f16.f16.f32 "
                 "{%0,%1,%2,%3}, {%4,%5,%6,%7}, {%8,%9}, {%0,%1,%2,%3};"
                 : "+f"(c[0]), "+f"(c[1]), "+f"(c[2]), "+f"(c[3])
                 : "r"(a[0]), "r"(a[1]), "r"(a[2]), "r"(a[3]),
                   "r"(b[0]), "r"(b[1]));
}

__global__ __launch_bounds__(256) void hgemm_kernel() {
    __shared__ __align__(16) __half As[BM * BK];
    __shared__ __align__(16) __half Bs[BN * BK];

    const int b = blockIdx.z;
    const __half* Ab = g_hq  + (size_t)b * CDIM * NDIM + (size_t)blockIdx.y * BM * NDIM;
    const __half* Bb = g_hkv + (size_t)b * CDIM * NDIM + (size_t)blockIdx.x * BN * NDIM;

    const int t    = threadIdx.x;
    const int lane = t & 31;
    const int wid  = t >> 5;
    const int wm   = wid & 3;         // 0..3 -> m offset
    const int wn   = wid >> 2;        // 0..1 -> n offset
    const int mbase = wm * 32;
    const int nbase = wn * 32;

    // global-load mapping: 8 threads per 128-B row
    const int ldRow   = t >> 3;       // 0..31
    const int ldChunk = t & 7;        // 0..7

    const uint32_t asU = (uint32_t)__cvta_generic_to_shared(As);
    const uint32_t bsU = (uint32_t)__cvta_generic_to_shared(Bs);

    float acc[2][4][4];
#pragma unroll
    for (int mi = 0; mi < 2; mi++)
#pragma unroll
        for (int ni = 0; ni < 4; ni++)
#pragma unroll
            for (int k = 0; k < 4; k++) acc[mi][ni][k] = 0.0f;

    // ---- load chunk 0 into smem ----
    {
        const __half* pa = Ab + ldChunk * 8;
        const __half* pb = Bb + ldChunk * 8;
#pragma unroll
        for (int i = 0; i < 4; i++) {
            int r = ldRow + i * 32;
            *(uint4*)&As[sw_idx(r, ldChunk)] = *(const uint4*)(pa + (size_t)r * NDIM);
        }
#pragma unroll
        for (int i = 0; i < 2; i++) {
            int r = ldRow + i * 32;
            *(uint4*)&Bs[sw_idx(r, ldChunk)] = *(const uint4*)(pb + (size_t)r * NDIM);
        }
    }
    __syncthreads();

    const int NCHUNK = NDIM / BK;   // 64
    for (int kk = 0; kk < NCHUNK; kk++) {
        const bool notlast = (kk + 1 < NCHUNK);
        uint4 pa[4], pb[2];
        if (notlast) {
            const __half* gpa = Ab + (kk + 1) * BK + ldChunk * 8;
            const __half* gpb = Bb + (kk + 1) * BK + ldChunk * 8;
#pragma unroll
            for (int i = 0; i < 4; i++)
                pa[i] = *(const uint4*)(gpa + (size_t)(ldRow + i * 32) * NDIM);
#pragma unroll
            for (int i = 0; i < 2; i++)
                pb[i] = *(const uint4*)(gpb + (size_t)(ldRow + i * 32) * NDIM);
        }

        // ---- compute 4 k16 steps from smem ----
#pragma unroll
        for (int s = 0; s < 4; s++) {
            uint32_t afr[2][4];
            uint32_t bfr[4][2];
#pragma unroll
            for (int mi = 0; mi < 2; mi++) {
                int row   = mbase + mi * 16 + (lane & 15);
                int chunk = 2 * s + (lane >> 4);
                uint32_t addr = asU + (uint32_t)(sw_idx(row, chunk) * 2);
                ldsm4(afr[mi][0], afr[mi][1], afr[mi][2], afr[mi][3], addr);
            }
#pragma unroll
            for (int p = 0; p < 2; p++) {
                int row   = nbase + p * 16 + (lane & 7) + ((lane >> 4) << 3);
                int chunk = 2 * s + ((lane >> 3) & 1);
                uint32_t addr = bsU + (uint32_t)(sw_idx(row, chunk) * 2);
                ldsm4(bfr[2 * p][0], bfr[2 * p][1], bfr[2 * p + 1][0], bfr[2 * p + 1][1], addr);
            }
#pragma unroll
            for (int mi = 0; mi < 2; mi++)
#pragma unroll
                for (int ni = 0; ni < 4; ni++)
                    mma16816(acc[mi][ni], afr[mi], bfr[ni]);
        }
        __syncthreads();

        if (notlast) {
#pragma unroll
            for (int i = 0; i < 4; i++)
                *(uint4*)&As[sw_idx(ldRow + i * 32, ldChunk)] = pa[i];
#pragma unroll
            for (int i = 0; i < 2; i++)
                *(uint4*)&Bs[sw_idx(ldRow + i * 32, ldChunk)] = pb[i];
            __syncthreads();
        }
    }

    // ---- epilogue: write fp32 energies ----
    float* Eb = g_energy + (size_t)b * CDIM * CDIM;
    const int c0 = blockIdx.y * BM + mbase;
    const int d0 = blockIdx.x * BN + nbase;
#pragma unroll
    for (int mi = 0; mi < 2; mi++) {
#pragma unroll
        for (int ni = 0; ni < 4; ni++) {
            int r = c0 + mi * 16 + (lane >> 2);
            int c = d0 + ni * 8 + ((lane & 3) << 1);
            Eb[(size_t)r * CDIM + c]           = acc[mi][ni][0];
            Eb[(size_t)r * CDIM + c + 1]       = acc[mi][ni][1];
            Eb[(size_t)(r + 8) * CDIM + c]     = acc[mi][ni][2];
            Eb[(size_t)(r + 8) * CDIM + c + 1] = acc[mi][ni][3];
        }
    }
}

// ---------------------------------------------------------------------------
// Fused attention-apply v2:
//  - approx min over row energies; select candidates e - min < 36
//    (covers exact threshold 34 + fp16-GEMM error with huge sigma margin)
//  - recompute candidate energies EXACTLY in fp32 (q row staged in smem)
//  - exact softmax weights over candidates (dropped terms < 2e-15 each)
//  - sparse gather out = sum w_d * kv[d,:], then per-64 softmax -> d_out
// One block (256 threads) per (b,c) row.
// ---------------------------------------------------------------------------
__global__ __launch_bounds__(256) void attn_apply_kernel(const float* __restrict__ q,
                                                         const float* __restrict__ kv,
                                                         float* __restrict__ out) {
    const int row = blockIdx.x;            // b*512 + c
    const int b   = row >> 9;
    const float* E    = g_energy + (size_t)row * CDIM;
    const float* qrow = q + (size_t)row * NDIM;
    const float* kvb  = kv + (size_t)b * CDIM * NDIM;
    float* O = out + (size_t)row * NDIM;

    __shared__ float sRed[8];
    __shared__ float sBuf[NDIM];    // q row, later reused for out row
    __shared__ float sEW[CDIM];     // exact energies, then weights
    __shared__ int   sIdx[CDIM];
    __shared__ int   sCount;

    const int t    = threadIdx.x;
    const int lane = t & 31;
    const int wp   = t >> 5;

    const float e0 = E[t];
    const float e1 = E[t + 256];

    // ---- approx min over the 512 energies ----
    float mn = fminf(e0, e1);
#pragma unroll
    for (int off = 16; off > 0; off >>= 1)
        mn = fminf(mn, __shfl_xor_sync(0xffffffffu, mn, off));
    if (lane == 0) sRed[wp] = mn;
    if (t == 0) sCount = 0;
    __syncthreads();
    mn = sRed[0];
#pragma unroll
    for (int i = 1; i < 8; i++) mn = fminf(mn, sRed[i]);

    // ---- candidate selection + stage q row in smem ----
    if (e0 - mn < 36.0f) { int k = atomicAdd(&sCount, 1); sIdx[k] = t; }
    if (e1 - mn < 36.0f) { int k = atomicAdd(&sCount, 1); sIdx[k] = t + 256; }
#pragma unroll
    for (int j = 0; j < 16; j++) sBuf[t + 256 * j] = qrow[t + 256 * j];
    __syncthreads();
    const int cnt = sCount;

    // ---- exact fp32 energies for candidates (one warp per candidate) ----
    for (int i = wp; i < cnt; i += 8) {
        const float* kr = kvb + (size_t)sIdx[i] * NDIM;
        float sum = 0.0f;
#pragma unroll 8
        for (int k = lane; k < NDIM; k += 32)
            sum += sBuf[k] * __ldg(&kr[k]);
#pragma unroll
        for (int off = 16; off > 0; off >>= 1)
            sum += __shfl_xor_sync(0xffffffffu, sum, off);
        if (lane == 0) sEW[i] = sum;
    }
    __syncthreads();

    // ---- exact min + denominator over candidates (all threads identical) ----
    float m = 3.4e38f;
    for (int i = 0; i < cnt; i++) m = fminf(m, sEW[i]);
    float s = 0.0f;
    for (int i = 0; i < cnt; i++) s += expf(m - sEW[i]);
    const float inv = 1.0f / s;
    __syncthreads();
    for (int i = t; i < cnt; i += 256)
        sEW[i] = expf(m - sEW[i]) * inv;   // in-place weights
    __syncthreads();

    // ---- sparse gather-accumulate ----
    float acc[16];
#pragma unroll
    for (int k = 0; k < 16; k++) acc[k] = 0.0f;
    for (int i = 0; i < cnt; i++) {
        const float* kr = kvb + (size_t)sIdx[i] * NDIM;
        const float w = sEW[i];
#pragma unroll
        for (int k = 0; k < 16; k++)
            acc[k] += w * __ldg(&kr[t + 256 * k]);
    }
    __syncthreads();   // done with sBuf-as-q
#pragma unroll
    for (int k = 0; k < 16; k++) sBuf[t + 256 * k] = acc[k];
    __syncthreads();

    // ---- final softmax over each 64-wide segment; 8 warps x 8 segments ----
#pragma unroll
    for (int sgi = 0; sgi < 8; sgi++) {
        const int base = (wp * 8 + sgi) * 64;
        const float v0 = sBuf[base + lane];
        const float v1 = sBuf[base + lane + 32];
        float mx = fmaxf(v0, v1);
#pragma unroll
        for (int off = 16; off > 0; off >>= 1)
            mx = fmaxf(mx, __shfl_xor_sync(0xffffffffu, mx, off));
        const float q0 = expf(v0 - mx);
        const float q1 = expf(v1 - mx);
        float ss = q0 + q1;
#pragma unroll
        for (int off = 16; off > 0; off >>= 1)
            ss += __shfl_xor_sync(0xffffffffu, ss, off);
        const float iv = 1.0f / ss;
        O[base + lane]      = q0 * iv;
        O[base + lane + 32] = q1 * iv;
    }
}

// ---------------------------------------------------------------------------
extern "C" void kernel_launch(void* const* d_in, const int* in_sizes, int n_in,
                              void* d_out, int out_size) {
    const float* kv = (const float*)d_in[0];  // x_training
    const float* q  = (const float*)d_in[1];  // x_pre
    float* out = (float*)d_out;

    convert_kernel<<<TOT_ELEMS / 4 / 256, 256>>>((const float4*)q, (const float4*)kv);

    dim3 g1(CDIM / BN, CDIM / BM, BATCH);   // (8, 4, 16)
    hgemm_kernel<<<g1, 256>>>();

    attn_apply_kernel<<<BATCH * CDIM, 256>>>(q, kv, out);
}